// round 3
// baseline (speedup 1.0000x reference)
#include <cuda_runtime.h>
#include <math.h>

// Problem constants (fixed shapes for this problem)
#define BB    2
#define NQQ   900
#define EE    256
#define NH    8
#define HDIM  32
#define HGRID 64
#define WGRID 64
#define HWK   4096
#define RPEH  512
#define LOG2E_F 1.4426950408889634f
#define QSCALE_F 0.17677669529663687f  // 1/sqrt(32)

// Scratch (no cudaMalloc allowed)
__device__ float g_q[BB * NQQ * EE];
__device__ float g_k[BB * HWK * EE];
__device__ float g_v[BB * HWK * EE];
__device__ float g_rx[BB * NH * NQQ * WGRID];   // [b][head][q][w]  (pre-scaled by log2e)
__device__ float g_ryT[BB * NH * HGRID * NQQ];  // [b][head][hidx][q]
__device__ float g_att[BB * NQQ * EE];

__device__ __forceinline__ float fexp2(float x) {
    float y;
    asm("ex2.approx.ftz.f32 %0, %1;" : "=f"(y) : "f"(x));
    return y;
}

__device__ __forceinline__ float logdelta(float d) {
    // sign(d) * log2(|d|+1) / 3
    float l = log2f(fabsf(d) + 1.0f) * (1.0f / 3.0f);
    return copysignf(l, d);
}

// ---------------------------------------------------------------------------
// Generic C[M,256] = alpha * (A[M,256] @ W[256,256] + bias[256])
// 64x64 tile, 256 threads, 4x4 per-thread register tile.
// ---------------------------------------------------------------------------
__global__ void gemm_bias_kernel(const float* __restrict__ A,
                                 const float* __restrict__ Wm,
                                 const float* __restrict__ bias,
                                 float* __restrict__ C,
                                 int M, float alpha)
{
    __shared__ __align__(16) float As[16][64];  // [kk][m]
    __shared__ __align__(16) float Ws[16][64];  // [kk][n]

    int tid = threadIdx.x;
    int m0 = blockIdx.x * 64;
    int n0 = blockIdx.y * 64;
    int tm = tid >> 4;       // 0..15
    int tn = tid & 15;       // 0..15
    int lrow = tid >> 2;     // 0..63  (A loader)
    int lkq  = tid & 3;      // 0..3
    int wkk  = tid >> 4;     // 0..15  (W loader)
    int wnq  = tid & 15;     // 0..15

    float acc[4][4] = {};

    for (int k0 = 0; k0 < 256; k0 += 16) {
        float4 av = make_float4(0.f, 0.f, 0.f, 0.f);
        int m = m0 + lrow;
        if (m < M) av = *(const float4*)&A[m * 256 + k0 + 4 * lkq];
        As[4 * lkq + 0][lrow] = av.x;
        As[4 * lkq + 1][lrow] = av.y;
        As[4 * lkq + 2][lrow] = av.z;
        As[4 * lkq + 3][lrow] = av.w;
        *(float4*)&Ws[wkk][4 * wnq] =
            *(const float4*)&Wm[(k0 + wkk) * 256 + n0 + 4 * wnq];
        __syncthreads();

        #pragma unroll
        for (int kk = 0; kk < 16; kk++) {
            float4 a = *(const float4*)&As[kk][4 * tm];
            float4 w = *(const float4*)&Ws[kk][4 * tn];
            float ar[4] = {a.x, a.y, a.z, a.w};
            float wr[4] = {w.x, w.y, w.z, w.w};
            #pragma unroll
            for (int i = 0; i < 4; i++)
                #pragma unroll
                for (int j = 0; j < 4; j++)
                    acc[i][j] = fmaf(ar[i], wr[j], acc[i][j]);
        }
        __syncthreads();
    }

    #pragma unroll
    for (int i = 0; i < 4; i++) {
        int m = m0 + 4 * tm + i;
        if (m < M) {
            float4 o;
            o.x = alpha * (acc[i][0] + bias[n0 + 4 * tn + 0]);
            o.y = alpha * (acc[i][1] + bias[n0 + 4 * tn + 1]);
            o.z = alpha * (acc[i][2] + bias[n0 + 4 * tn + 2]);
            o.w = alpha * (acc[i][3] + bias[n0 + 4 * tn + 3]);
            *(float4*)&C[m * 256 + n0 + 4 * tn] = o;
        }
    }
}

// ---------------------------------------------------------------------------
// RPE MLP: one block per (b,q); 128 threads = 2 axes x 64 positions.
// hidden = relu(d1*W1[0,h] + d2*W1[1,h] + b1[h]);  out[head] = hidden @ W2
// Outputs pre-scaled by log2(e) so attention softmax can use exp2.
// ---------------------------------------------------------------------------
__global__ void rpe_kernel(const float* __restrict__ refp,
                           const float* __restrict__ W1x, const float* __restrict__ b1x,
                           const float* __restrict__ W2x,
                           const float* __restrict__ W1y, const float* __restrict__ b1y,
                           const float* __restrict__ W2y)
{
    __shared__ __align__(16) float sW1a[2][RPEH];
    __shared__ __align__(16) float sW1b[2][RPEH];
    __shared__ __align__(16) float sb1[2][RPEH];
    __shared__ __align__(16) float sW2[2][RPEH * 8];

    int tid = threadIdx.x;
    for (int i = tid; i < RPEH; i += 128) {
        sW1a[0][i] = W1x[i];        sW1b[0][i] = W1x[RPEH + i];  sb1[0][i] = b1x[i];
        sW1a[1][i] = W1y[i];        sW1b[1][i] = W1y[RPEH + i];  sb1[1][i] = b1y[i];
    }
    for (int i = tid; i < RPEH * 8; i += 128) {
        sW2[0][i] = W2x[i];
        sW2[1][i] = W2y[i];
    }
    __syncthreads();

    int bq = blockIdx.x;
    int b = bq / NQQ;
    int q = bq % NQQ;
    float4 r = *(const float4*)&refp[bq * 4];  // cx, cy, bw, bh

    int axis = tid >> 6;   // 0=x, 1=y
    int p = tid & 63;

    float ctr = axis ? r.y : r.x;
    float sz  = axis ? r.w : r.z;
    float lo = (ctr - 0.5f * sz) * 1024.0f;  // (W or H) * STRIDE = 64*16
    float hi = (ctr + 0.5f * sz) * 1024.0f;
    float pos = (p + 0.5f) * 16.0f;
    float d1 = logdelta(lo - pos);
    float d2 = logdelta(hi - pos);

    const float* wa = sW1a[axis];
    const float* wb = sW1b[axis];
    const float* bv = sb1[axis];
    const float* w2 = sW2[axis];

    float acc[8] = {};
    for (int hh = 0; hh < RPEH; hh++) {
        float v = fmaf(d1, wa[hh], fmaf(d2, wb[hh], bv[hh]));
        v = fmaxf(v, 0.0f);
        float4 wlo = *(const float4*)&w2[hh * 8];
        float4 whi = *(const float4*)&w2[hh * 8 + 4];
        acc[0] = fmaf(v, wlo.x, acc[0]);
        acc[1] = fmaf(v, wlo.y, acc[1]);
        acc[2] = fmaf(v, wlo.z, acc[2]);
        acc[3] = fmaf(v, wlo.w, acc[3]);
        acc[4] = fmaf(v, whi.x, acc[4]);
        acc[5] = fmaf(v, whi.y, acc[5]);
        acc[6] = fmaf(v, whi.z, acc[6]);
        acc[7] = fmaf(v, whi.w, acc[7]);
    }

    #pragma unroll
    for (int hd = 0; hd < 8; hd++) {
        float val = acc[hd] * LOG2E_F;
        if (axis == 0)
            g_rx[((b * NH + hd) * NQQ + q) * WGRID + p] = val;
        else
            g_ryT[((b * NH + hd) * HGRID + p) * NQQ + q] = val;
    }
}

// ---------------------------------------------------------------------------
// Fused attention: block = (qtile of 64, head, batch), 128 threads.
// Streams 32-key chunks (half an image row => constant y-bias per chunk).
// Online softmax in base-2 (scales pre-folded).
// ---------------------------------------------------------------------------
__global__ void attn_kernel(float* __restrict__ outp)
{
    __shared__ __align__(16) float QsT[32][64];   // [d][q]
    __shared__ __align__(16) float KsT[32][32];   // [d][k]
    __shared__ __align__(16) float Vs[32][32];    // [k][d]
    __shared__ __align__(16) float ST[32][68];    // [k][q], padded
    __shared__ __align__(16) float rxs[64][64];   // [q][w]
    __shared__ float rycol[64];
    __shared__ float mrow[64], lrow[64], srow[64];

    int tid = threadIdx.x;
    int qt = blockIdx.x, h = blockIdx.y, b = blockIdx.z;
    int q0 = qt * 64;
    int tq = tid >> 3;   // 0..15 (query group)
    int tx = tid & 7;    // 0..7  (key group in GEMM1 / d group in GEMM2)

    if (tid < 64) { mrow[tid] = -1e30f; lrow[tid] = 0.0f; }

    // Load Q tile (transposed). Padded queries -> 0.
    {
        int d = tid & 31, qq = tid >> 5;
        for (int r = 0; r < 16; r++) {
            int q = qq + 4 * r;
            int qg = q0 + q;
            float v = 0.0f;
            if (qg < NQQ) v = g_q[(b * NQQ + qg) * EE + h * HDIM + d];
            QsT[d][q] = v;
        }
    }
    // Load rx tile [64 q][64 w]
    for (int idx = tid; idx < 64 * 16; idx += 128) {
        int q = idx >> 4, wq = idx & 15;
        int qg = min(q0 + q, NQQ - 1);
        *(float4*)&rxs[q][4 * wq] =
            *(const float4*)&g_rx[((b * NH + h) * NQQ + qg) * WGRID + 4 * wq];
    }
    __syncthreads();

    float o[4][4] = {};

    for (int ch = 0; ch < 128; ch++) {
        int k0 = ch * 32;
        int c = ch >> 1;             // image row (y index)
        int w0 = (ch & 1) * 32;      // x offset within row

        // Load K, V chunk (coalesced over d)
        {
            int d = tid & 31, kk0 = tid >> 5;
            for (int r = 0; r < 8; r++) {
                int kk = kk0 + 4 * r;
                int gi = (b * HWK + k0 + kk) * EE + h * HDIM + d;
                KsT[d][kk] = g_k[gi];
                Vs[kk][d] = g_v[gi];
            }
        }
        if (tid < 64) {
            int qg = min(q0 + tid, NQQ - 1);
            rycol[tid] = g_ryT[((b * NH + h) * HGRID + c) * NQQ + qg];
        }
        __syncthreads();

        // GEMM1: S[64q][32k] = Q @ K^T   (per-thread 4x4)
        float s[4][4] = {};
        #pragma unroll
        for (int kk = 0; kk < 32; kk++) {
            float4 qv = *(const float4*)&QsT[kk][4 * tq];
            float4 kv = *(const float4*)&KsT[kk][4 * tx];
            float qr[4] = {qv.x, qv.y, qv.z, qv.w};
            float kr[4] = {kv.x, kv.y, kv.z, kv.w};
            #pragma unroll
            for (int i = 0; i < 4; i++)
                #pragma unroll
                for (int j = 0; j < 4; j++)
                    s[i][j] = fmaf(qr[i], kr[j], s[i][j]);
        }
        // Bias add + transposed store
        #pragma unroll
        for (int j = 0; j < 4; j++) {
            float4 sv;
            sv.x = s[0][j] + rycol[4 * tq + 0] + rxs[4 * tq + 0][w0 + 4 * tx + j];
            sv.y = s[1][j] + rycol[4 * tq + 1] + rxs[4 * tq + 1][w0 + 4 * tx + j];
            sv.z = s[2][j] + rycol[4 * tq + 2] + rxs[4 * tq + 2][w0 + 4 * tx + j];
            sv.w = s[3][j] + rycol[4 * tq + 3] + rxs[4 * tq + 3][w0 + 4 * tx + j];
            *(float4*)&ST[4 * tx + j][4 * tq] = sv;
        }
        __syncthreads();

        // Online softmax over this chunk (64 threads, one per query column)
        if (tid < 64) {
            int q = tid;
            float mold = mrow[q];
            float mx = mold;
            #pragma unroll
            for (int kk = 0; kk < 32; kk++) mx = fmaxf(mx, ST[kk][q]);
            float scl = fexp2(mold - mx);
            float sum = 0.0f;
            #pragma unroll
            for (int kk = 0; kk < 32; kk++) {
                float p = fexp2(ST[kk][q] - mx);
                ST[kk][q] = p;
                sum += p;
            }
            mrow[q] = mx;
            lrow[q] = lrow[q] * scl + sum;
            srow[q] = scl;
        }
        __syncthreads();

        // GEMM2: O[64q][32d] = scl*O + P @ V  (per-thread 4x4)
        {
            float sc[4];
            #pragma unroll
            for (int i = 0; i < 4; i++) sc[i] = srow[4 * tq + i];
            #pragma unroll
            for (int i = 0; i < 4; i++)
                #pragma unroll
                for (int j = 0; j < 4; j++)
                    o[i][j] *= sc[i];
            #pragma unroll
            for (int kk = 0; kk < 32; kk++) {
                float4 pv = *(const float4*)&ST[kk][4 * tq];
                float4 vv = *(const float4*)&Vs[kk][4 * tx];
                float pr[4] = {pv.x, pv.y, pv.z, pv.w};
                float vr[4] = {vv.x, vv.y, vv.z, vv.w};
                #pragma unroll
                for (int i = 0; i < 4; i++)
                    #pragma unroll
                    for (int j = 0; j < 4; j++)
                        o[i][j] = fmaf(pr[i], vr[j], o[i][j]);
            }
        }
        __syncthreads();
    }

    // Normalize and write
    #pragma unroll
    for (int i = 0; i < 4; i++) {
        int q = q0 + 4 * tq + i;
        if (q < NQQ) {
            float inv = 1.0f / lrow[4 * tq + i];
            float4 ov = make_float4(o[i][0] * inv, o[i][1] * inv,
                                    o[i][2] * inv, o[i][3] * inv);
            *(float4*)&outp[(b * NQQ + q) * EE + h * HDIM + 4 * tx] = ov;
        }
    }
}

// ---------------------------------------------------------------------------
extern "C" void kernel_launch(void* const* d_in, const int* in_sizes, int n_in,
                              void* d_out, int out_size)
{
    const float* query = (const float*)d_in[0];
    const float* key   = (const float*)d_in[1];
    const float* value = (const float*)d_in[2];
    const float* refp  = (const float*)d_in[3];
    const float* Wq = (const float*)d_in[4];  const float* bq = (const float*)d_in[5];
    const float* Wk = (const float*)d_in[6];  const float* bk = (const float*)d_in[7];
    const float* Wv = (const float*)d_in[8];  const float* bv = (const float*)d_in[9];
    const float* Wo = (const float*)d_in[10]; const float* bo = (const float*)d_in[11];
    const float* W1x = (const float*)d_in[12]; const float* b1x = (const float*)d_in[13];
    const float* W2x = (const float*)d_in[14];
    const float* W1y = (const float*)d_in[15]; const float* b1y = (const float*)d_in[16];
    const float* W2y = (const float*)d_in[17];
    float* out = (float*)d_out;

    float *pq, *pk, *pv, *patt;
    cudaGetSymbolAddress((void**)&pq, g_q);
    cudaGetSymbolAddress((void**)&pk, g_k);
    cudaGetSymbolAddress((void**)&pv, g_v);
    cudaGetSymbolAddress((void**)&patt, g_att);

    // Projections (Q gets softmax scale * log2e folded in)
    gemm_bias_kernel<<<dim3(29, 4), 256>>>(query, Wq, bq, pq, BB * NQQ,
                                           QSCALE_F * LOG2E_F);
    gemm_bias_kernel<<<dim3(128, 4), 256>>>(key, Wk, bk, pk, BB * HWK, 1.0f);
    gemm_bias_kernel<<<dim3(128, 4), 256>>>(value, Wv, bv, pv, BB * HWK, 1.0f);

    // RPE factors
    rpe_kernel<<<BB * NQQ, 128>>>(refp, W1x, b1x, W2x, W1y, b1y, W2y);

    // Fused attention
    attn_kernel<<<dim3(15, NH, BB), 128>>>(patt);

    // Output projection
    gemm_bias_kernel<<<dim3(29, 4), 256>>>(patt, Wo, bo, out, BB * NQQ, 1.0f);
}

// round 4
// speedup vs baseline: 1.2726x; 1.2726x over previous
#include <cuda_runtime.h>
#include <math.h>

#define BB    2
#define NQQ   900
#define EE    256
#define NH    8
#define HDIM  32
#define HWK   4096
#define RPEH  512
#define LOG2E_F 1.4426950408889634f
#define QSCALE_F 0.17677669529663687f

__device__ float g_qT[BB * NH * HDIM * NQQ];   // [(b*8+h)*32+d][900]
__device__ float g_kT[BB * NH * HDIM * HWK];   // [(b*8+h)*32+d][4096]
__device__ float g_v [BB * HWK * EE];
__device__ float g_rx[BB * NH * NQQ * 64];     // [bh][q][w], pre-scaled by log2e
__device__ float g_ryT[BB * NH * 64 * NQQ];    // [bh][c][q]
__device__ float g_att[BB * NQQ * EE];

typedef unsigned long long u64;

__device__ __forceinline__ float fexp2(float x) {
    float y; asm("ex2.approx.ftz.f32 %0, %1;" : "=f"(y) : "f"(x)); return y;
}
__device__ __forceinline__ u64 ffma2(u64 a, u64 b, u64 c) {
    u64 d; asm("fma.rn.f32x2 %0, %1, %2, %3;" : "=l"(d) : "l"(a), "l"(b), "l"(c)); return d;
}
__device__ __forceinline__ u64 fmul2(u64 a, u64 b) {
    u64 d; asm("mul.rn.f32x2 %0, %1, %2;" : "=l"(d) : "l"(a), "l"(b)); return d;
}
__device__ __forceinline__ u64 dup2(float x) {
    u64 r; asm("mov.b64 %0, {%1, %1};" : "=l"(r) : "f"(x)); return r;
}
__device__ __forceinline__ float2 unpk2(u64 v) {
    float2 r; asm("mov.b64 {%0, %1}, %2;" : "=f"(r.x), "=f"(r.y) : "l"(v)); return r;
}
__device__ __forceinline__ float logdelta(float d) {
    float l = log2f(fabsf(d) + 1.0f) * (1.0f / 3.0f);
    return copysignf(l, d);
}

// ---------------------------------------------------------------------------
// C = alpha*(A[M,256] @ W[256,256] + bias).
// TMODE 0: row-major out. TMODE 1: per-head transposed out:
//   C[((m/plane)*8 + n/32)*32 + n%32][m%plane]   (plane = NQQ or HWK)
// ---------------------------------------------------------------------------
template<int TMODE>
__global__ void gemm_bias_kernel(const float* __restrict__ A,
                                 const float* __restrict__ Wm,
                                 const float* __restrict__ bias,
                                 float* __restrict__ C,
                                 int M, int plane, float alpha)
{
    __shared__ __align__(16) float As[16][64];
    __shared__ __align__(16) float Ws[16][64];

    int tid = threadIdx.x;
    int m0 = blockIdx.x * 64;
    int n0 = blockIdx.y * 64;
    int tm = tid >> 4, tn = tid & 15;
    int lrow = tid >> 2, lkq = tid & 3;
    int wkk = tid >> 4, wnq = tid & 15;

    u64 acc2[4][2] = {};

    for (int k0 = 0; k0 < 256; k0 += 16) {
        float4 av = make_float4(0.f, 0.f, 0.f, 0.f);
        int m = m0 + lrow;
        if (m < M) av = *(const float4*)&A[m * 256 + k0 + 4 * lkq];
        As[4 * lkq + 0][lrow] = av.x;
        As[4 * lkq + 1][lrow] = av.y;
        As[4 * lkq + 2][lrow] = av.z;
        As[4 * lkq + 3][lrow] = av.w;
        *(float4*)&Ws[wkk][4 * wnq] =
            *(const float4*)&Wm[(k0 + wkk) * 256 + n0 + 4 * wnq];
        __syncthreads();

        #pragma unroll
        for (int kk = 0; kk < 16; kk++) {
            float4 a = *(const float4*)&As[kk][4 * tm];
            ulonglong2 w = *(const ulonglong2*)&Ws[kk][4 * tn];
            float ar[4] = {a.x, a.y, a.z, a.w};
            #pragma unroll
            for (int i = 0; i < 4; i++) {
                u64 ad = dup2(ar[i]);
                acc2[i][0] = ffma2(ad, w.x, acc2[i][0]);
                acc2[i][1] = ffma2(ad, w.y, acc2[i][1]);
            }
        }
        __syncthreads();
    }

    float4 bv = *(const float4*)&bias[n0 + 4 * tn];
    float o[4][4];
    #pragma unroll
    for (int i = 0; i < 4; i++) {
        float2 lo = unpk2(acc2[i][0]);
        float2 hi = unpk2(acc2[i][1]);
        o[i][0] = alpha * (lo.x + bv.x);
        o[i][1] = alpha * (lo.y + bv.y);
        o[i][2] = alpha * (hi.x + bv.z);
        o[i][3] = alpha * (hi.y + bv.w);
    }

    if (TMODE == 0) {
        #pragma unroll
        for (int i = 0; i < 4; i++) {
            int m = m0 + 4 * tm + i;
            if (m < M)
                *(float4*)&C[m * 256 + n0 + 4 * tn] =
                    make_float4(o[i][0], o[i][1], o[i][2], o[i][3]);
        }
    } else {
        __shared__ float Ts[64][65];
        #pragma unroll
        for (int i = 0; i < 4; i++)
            #pragma unroll
            for (int j = 0; j < 4; j++)
                Ts[4 * tn + j][4 * tm + i] = o[i][j];
        __syncthreads();
        for (int idx = tid; idx < 4096; idx += 256) {
            int ml = idx & 63, nl = idx >> 6;
            int m = m0 + ml;
            if (m < M) {
                int bq = m / plane;
                int mm = m - bq * plane;
                int n = n0 + nl;
                int row = (bq * NH + (n >> 5)) * 32 + (n & 31);
                C[(long long)row * plane + mm] = Ts[nl][ml];
            }
        }
    }
}

// ---------------------------------------------------------------------------
// RPE MLP: 256 threads = 4 (b,q) x 2 axes x 32 lanes; 2 positions/thread.
// ---------------------------------------------------------------------------
__global__ void rpe_kernel(const float* __restrict__ refp,
                           const float* __restrict__ W1x, const float* __restrict__ b1x,
                           const float* __restrict__ W2x,
                           const float* __restrict__ W1y, const float* __restrict__ b1y,
                           const float* __restrict__ W2y)
{
    __shared__ __align__(16) float2 sW1[2][RPEH];
    __shared__ __align__(16) float sb1[2][RPEH];
    __shared__ __align__(16) float sW2[2][RPEH * 8];

    int tid = threadIdx.x;
    for (int i = tid; i < RPEH; i += 256) {
        sW1[0][i] = make_float2(W1x[i], W1x[RPEH + i]);  sb1[0][i] = b1x[i];
        sW1[1][i] = make_float2(W1y[i], W1y[RPEH + i]);  sb1[1][i] = b1y[i];
    }
    for (int i = tid; i < RPEH * 8; i += 256) {
        sW2[0][i] = W2x[i];
        sW2[1][i] = W2y[i];
    }
    __syncthreads();

    int bq = blockIdx.x * 4 + (tid >> 6);
    int b = bq / NQQ, q = bq - b * NQQ;
    float4 r = *(const float4*)&refp[bq * 4];
    int axis = (tid >> 5) & 1;
    int lane = tid & 31;

    float ctr = axis ? r.y : r.x;
    float sz  = axis ? r.w : r.z;
    float lo = (ctr - 0.5f * sz) * 1024.0f;
    float hi = (ctr + 0.5f * sz) * 1024.0f;
    float posA = (lane + 0.5f) * 16.0f;
    float posB = (lane + 32.5f) * 16.0f;
    float d1a = logdelta(lo - posA), d2a = logdelta(hi - posA);
    float d1b = logdelta(lo - posB), d2b = logdelta(hi - posB);

    const float2* w1 = sW1[axis];
    const float* bb = sb1[axis];
    const float* w2 = sW2[axis];

    u64 a0[4] = {}, a1[4] = {};
    #pragma unroll 4
    for (int hh = 0; hh < RPEH; hh++) {
        float2 w = w1[hh];
        float bvf = bb[hh];
        float v0 = fmaxf(fmaf(d1a, w.x, fmaf(d2a, w.y, bvf)), 0.0f);
        float v1 = fmaxf(fmaf(d1b, w.x, fmaf(d2b, w.y, bvf)), 0.0f);
        u64 v0d = dup2(v0), v1d = dup2(v1);
        ulonglong2 wlo = *(const ulonglong2*)&w2[hh * 8];
        ulonglong2 whi = *(const ulonglong2*)&w2[hh * 8 + 4];
        a0[0] = ffma2(v0d, wlo.x, a0[0]);  a0[1] = ffma2(v0d, wlo.y, a0[1]);
        a0[2] = ffma2(v0d, whi.x, a0[2]);  a0[3] = ffma2(v0d, whi.y, a0[3]);
        a1[0] = ffma2(v1d, wlo.x, a1[0]);  a1[1] = ffma2(v1d, wlo.y, a1[1]);
        a1[2] = ffma2(v1d, whi.x, a1[2]);  a1[3] = ffma2(v1d, whi.y, a1[3]);
    }

    float o0[8], o1[8];
    #pragma unroll
    for (int c = 0; c < 4; c++) {
        float2 x0 = unpk2(a0[c]); float2 x1 = unpk2(a1[c]);
        o0[2*c] = x0.x * LOG2E_F;  o0[2*c+1] = x0.y * LOG2E_F;
        o1[2*c] = x1.x * LOG2E_F;  o1[2*c+1] = x1.y * LOG2E_F;
    }
    long long bh = (long long)b * NH;
    #pragma unroll
    for (int hd = 0; hd < 8; hd++) {
        if (axis == 0) {
            g_rx[((bh + hd) * NQQ + q) * 64 + lane]      = o0[hd];
            g_rx[((bh + hd) * NQQ + q) * 64 + lane + 32] = o1[hd];
        } else {
            g_ryT[((bh + hd) * 64 + lane)      * NQQ + q] = o0[hd];
            g_ryT[((bh + hd) * 64 + lane + 32) * NQQ + q] = o1[hd];
        }
    }
}

// ---------------------------------------------------------------------------
// Fused attention: block=(qtile 64, head, batch), 128 threads.
// Double-buffered K/V/ry with register prefetch; FFMA2 GEMMs; base-2 softmax.
// ---------------------------------------------------------------------------
#define ATTN_SMEM_FLOATS 12992
__global__ void __launch_bounds__(128, 2) attn_kernel(float* __restrict__ outp)
{
    extern __shared__ __align__(16) float sm[];
    float* QsT  = sm;            // [32][64]
    float* KsT  = sm + 2048;     // 2 x [32 d][32 k]
    float* Vs   = sm + 4096;     // 2 x [32 k][32 d]
    float* ST   = sm + 6144;     // [32 k][68]
    float* rxsT = sm + 8320;     // [64 w][68]
    float* ryb  = sm + 12672;    // 2 x [64]
    float* mrow = sm + 12800;
    float* lrow = sm + 12864;
    float* srow = sm + 12928;

    int tid = threadIdx.x;
    int qt = blockIdx.x, h = blockIdx.y, b = blockIdx.z;
    int q0 = qt * 64;
    int tq = tid >> 3, tx = tid & 7;
    long long bh = (long long)b * NH + h;

    if (tid < 64) { mrow[tid] = -1e30f; lrow[tid] = 0.0f; }

    // Q tile: coalesced rows of g_qT, conflict-free stores. (900%4==0 => safe)
    {
        int q4 = (tid & 15) * 4;
        int dr = tid >> 4;
        const float* qb = g_qT + bh * 32 * NQQ;
        #pragma unroll
        for (int r2 = 0; r2 < 4; r2++) {
            int d = dr + 8 * r2;
            float4 val = make_float4(0.f, 0.f, 0.f, 0.f);
            if (q0 + q4 < NQQ) val = *(const float4*)&qb[d * NQQ + q0 + q4];
            *(float4*)&QsT[d * 64 + q4] = val;
        }
    }
    // rx tile, transposed into [w][q] (pad 68)
    {
        const float* rxb = g_rx + bh * NQQ * 64;
        for (int idx = tid; idx < 64 * 16; idx += 128) {
            int q = idx >> 4, w4 = (idx & 15) * 4;
            int qg = min(q0 + q, NQQ - 1);
            float4 v = *(const float4*)&rxb[qg * 64 + w4];
            rxsT[(w4 + 0) * 68 + q] = v.x;
            rxsT[(w4 + 1) * 68 + q] = v.y;
            rxsT[(w4 + 2) * 68 + q] = v.z;
            rxsT[(w4 + 3) * 68 + q] = v.w;
        }
    }

    int lk4 = (tid & 7) * 4;
    int lr16 = tid >> 3;         // 0..15
    const float* kb = g_kT + bh * 32 * HWK;
    const float* vb = g_v + (long long)b * HWK * EE + h * HDIM;
    int ryq = min(q0 + tid, NQQ - 1);

    // Prologue: chunk 0 -> buffer 0
    *(float4*)&KsT[lr16 * 32 + lk4]        = *(const float4*)&kb[lr16 * HWK + lk4];
    *(float4*)&KsT[(lr16 + 16) * 32 + lk4] = *(const float4*)&kb[(lr16 + 16) * HWK + lk4];
    *(float4*)&Vs[lr16 * 32 + lk4]         = *(const float4*)&vb[lr16 * EE + lk4];
    *(float4*)&Vs[(lr16 + 16) * 32 + lk4]  = *(const float4*)&vb[(lr16 + 16) * EE + lk4];
    if (tid < 64) ryb[tid] = g_ryT[bh * 64 * NQQ + ryq];
    __syncthreads();

    u64 o2[4][2] = {};

    for (int ch = 0; ch < 128; ch++) {
        int buf = ch & 1;
        int w0 = buf * 32;
        const float* Kc = KsT + buf * 1024;
        const float* Vc = Vs + buf * 1024;
        const float* ryc = ryb + buf * 64;

        // Prefetch chunk ch+1 into registers
        float4 kr0, kr1, vr0, vr1; float ryr = 0.0f;
        if (ch < 127) {
            int k0n = (ch + 1) * 32;
            kr0 = *(const float4*)&kb[lr16 * HWK + k0n + lk4];
            kr1 = *(const float4*)&kb[(lr16 + 16) * HWK + k0n + lk4];
            vr0 = *(const float4*)&vb[(k0n + lr16) * EE + lk4];
            vr1 = *(const float4*)&vb[(k0n + lr16 + 16) * EE + lk4];
            if (tid < 64)
                ryr = g_ryT[(bh * 64 + ((ch + 1) >> 1)) * NQQ + ryq];
        }

        // GEMM1: S[64q][32k] = Q @ K^T, FFMA2 pairs along k
        u64 s2[4][2] = {};
        #pragma unroll 8
        for (int kk = 0; kk < 32; kk++) {
            float4 qv = *(const float4*)&QsT[kk * 64 + 4 * tq];
            ulonglong2 kp = *(const ulonglong2*)&Kc[kk * 32 + 4 * tx];
            float qr[4] = {qv.x, qv.y, qv.z, qv.w};
            #pragma unroll
            for (int i = 0; i < 4; i++) {
                u64 qd = dup2(qr[i]);
                s2[i][0] = ffma2(qd, kp.x, s2[i][0]);
                s2[i][1] = ffma2(qd, kp.y, s2[i][1]);
            }
        }
        float s[4][4];
        #pragma unroll
        for (int i = 0; i < 4; i++) {
            float2 a = unpk2(s2[i][0]); float2 c = unpk2(s2[i][1]);
            s[i][0] = a.x; s[i][1] = a.y; s[i][2] = c.x; s[i][3] = c.y;
        }
        float ry4[4];
        #pragma unroll
        for (int i = 0; i < 4; i++) ry4[i] = ryc[4 * tq + i];
        #pragma unroll
        for (int j = 0; j < 4; j++) {
            float4 rv = *(const float4*)&rxsT[(w0 + 4 * tx + j) * 68 + 4 * tq];
            float4 sv;
            sv.x = s[0][j] + ry4[0] + rv.x;
            sv.y = s[1][j] + ry4[1] + rv.y;
            sv.z = s[2][j] + ry4[2] + rv.z;
            sv.w = s[3][j] + ry4[3] + rv.w;
            *(float4*)&ST[(4 * tx + j) * 68 + 4 * tq] = sv;
        }
        __syncthreads();

        // Softmax: 2 threads per query
        {
            int q = tid >> 1, hf = tid & 1;
            float mold = mrow[q];
            float mx = mold;
            #pragma unroll
            for (int s5 = 0; s5 < 16; s5++)
                mx = fmaxf(mx, ST[(2 * s5 + hf) * 68 + q]);
            mx = fmaxf(mx, __shfl_xor_sync(0xffffffffu, mx, 1));
            float sum = 0.0f;
            #pragma unroll
            for (int s5 = 0; s5 < 16; s5++) {
                int kk = 2 * s5 + hf;
                float p = fexp2(ST[kk * 68 + q] - mx);
                ST[kk * 68 + q] = p;
                sum += p;
            }
            sum += __shfl_xor_sync(0xffffffffu, sum, 1);
            if (hf == 0) {
                mrow[q] = mx;
                float scl = fexp2(mold - mx);
                lrow[q] = lrow[q] * scl + sum;
                srow[q] = scl;
            }
        }
        __syncthreads();

        // Store prefetched chunk into other buffer (no reader until next iter)
        if (ch < 127) {
            float* Kn = KsT + (buf ^ 1) * 1024;
            float* Vn = Vs + (buf ^ 1) * 1024;
            *(float4*)&Kn[lr16 * 32 + lk4]        = kr0;
            *(float4*)&Kn[(lr16 + 16) * 32 + lk4] = kr1;
            *(float4*)&Vn[lr16 * 32 + lk4]        = vr0;
            *(float4*)&Vn[(lr16 + 16) * 32 + lk4] = vr1;
            if (tid < 64) ryb[(buf ^ 1) * 64 + tid] = ryr;
        }

        // GEMM2: O = scl*O + P @ V, FFMA2 pairs along d
        {
            u64 sc[4];
            #pragma unroll
            for (int i = 0; i < 4; i++) sc[i] = dup2(srow[4 * tq + i]);
            #pragma unroll
            for (int i = 0; i < 4; i++) {
                o2[i][0] = fmul2(o2[i][0], sc[i]);
                o2[i][1] = fmul2(o2[i][1], sc[i]);
            }
            #pragma unroll 8
            for (int kk = 0; kk < 32; kk++) {
                float4 pv = *(const float4*)&ST[kk * 68 + 4 * tq];
                ulonglong2 vp = *(const ulonglong2*)&Vc[kk * 32 + 4 * tx];
                float pr[4] = {pv.x, pv.y, pv.z, pv.w};
                #pragma unroll
                for (int i = 0; i < 4; i++) {
                    u64 pd = dup2(pr[i]);
                    o2[i][0] = ffma2(pd, vp.x, o2[i][0]);
                    o2[i][1] = ffma2(pd, vp.y, o2[i][1]);
                }
            }
        }
        __syncthreads();
    }

    #pragma unroll
    for (int i = 0; i < 4; i++) {
        int q = q0 + 4 * tq + i;
        if (q < NQQ) {
            float inv = 1.0f / lrow[4 * tq + i];
            float2 lo = unpk2(o2[i][0]);
            float2 hi = unpk2(o2[i][1]);
            *(float4*)&outp[(b * NQQ + q) * EE + h * HDIM + 4 * tx] =
                make_float4(lo.x * inv, lo.y * inv, hi.x * inv, hi.y * inv);
        }
    }
}

// ---------------------------------------------------------------------------
extern "C" void kernel_launch(void* const* d_in, const int* in_sizes, int n_in,
                              void* d_out, int out_size)
{
    const float* query = (const float*)d_in[0];
    const float* key   = (const float*)d_in[1];
    const float* value = (const float*)d_in[2];
    const float* refp  = (const float*)d_in[3];
    const float* Wq = (const float*)d_in[4];  const float* bq = (const float*)d_in[5];
    const float* Wk = (const float*)d_in[6];  const float* bk = (const float*)d_in[7];
    const float* Wv = (const float*)d_in[8];  const float* bv = (const float*)d_in[9];
    const float* Wo = (const float*)d_in[10]; const float* bo = (const float*)d_in[11];
    const float* W1x = (const float*)d_in[12]; const float* b1x = (const float*)d_in[13];
    const float* W2x = (const float*)d_in[14];
    const float* W1y = (const float*)d_in[15]; const float* b1y = (const float*)d_in[16];
    const float* W2y = (const float*)d_in[17];
    float* out = (float*)d_out;

    float *pqT, *pkT, *pv, *patt;
    cudaGetSymbolAddress((void**)&pqT, g_qT);
    cudaGetSymbolAddress((void**)&pkT, g_kT);
    cudaGetSymbolAddress((void**)&pv, g_v);
    cudaGetSymbolAddress((void**)&patt, g_att);

    static int attr_done = 0;
    if (!attr_done) {
        cudaFuncSetAttribute(attn_kernel,
                             cudaFuncAttributeMaxDynamicSharedMemorySize,
                             ATTN_SMEM_FLOATS * 4);
        attr_done = 1;
    }

    gemm_bias_kernel<1><<<dim3(29, 4), 256>>>(query, Wq, bq, pqT, BB * NQQ,
                                              NQQ, QSCALE_F * LOG2E_F);
    gemm_bias_kernel<1><<<dim3(128, 4), 256>>>(key, Wk, bk, pkT, BB * HWK,
                                               HWK, 1.0f);
    gemm_bias_kernel<0><<<dim3(128, 4), 256>>>(value, Wv, bv, pv, BB * HWK,
                                               HWK, 1.0f);

    rpe_kernel<<<450, 256>>>(refp, W1x, b1x, W2x, W1y, b1y, W2y);

    attn_kernel<<<dim3(15, NH, BB), 128, ATTN_SMEM_FLOATS * 4>>>(patt);

    gemm_bias_kernel<0><<<dim3(29, 4), 256>>>(patt, Wo, bo, out, BB * NQQ,
                                              NQQ, 1.0f);
}

// round 5
// speedup vs baseline: 1.2740x; 1.0011x over previous
#include <cuda_runtime.h>
#include <math.h>

#define BB    2
#define NQQ   900
#define EE    256
#define NH    8
#define HDIM  32
#define HWK   4096
#define RPEH  512
#define LOG2E_F 1.4426950408889634f
#define QSCALE_F 0.17677669529663687f

__device__ float g_qT[BB * NH * HDIM * NQQ];   // [(b*8+h)*32+d][900]
__device__ float g_kT[BB * NH * HDIM * HWK];   // [(b*8+h)*32+d][4096]
__device__ float g_v [BB * HWK * EE];
__device__ float g_rx[BB * NH * NQQ * 64];     // [bh][q][w], pre-scaled by log2e
__device__ float g_ryT[BB * NH * 64 * NQQ];    // [bh][c][q]
__device__ float g_att[BB * NQQ * EE];

typedef unsigned long long u64;

__device__ __forceinline__ float fexp2(float x) {
    float y; asm("ex2.approx.ftz.f32 %0, %1;" : "=f"(y) : "f"(x)); return y;
}
__device__ __forceinline__ u64 ffma2(u64 a, u64 b, u64 c) {
    u64 d; asm("fma.rn.f32x2 %0, %1, %2, %3;" : "=l"(d) : "l"(a), "l"(b), "l"(c)); return d;
}
__device__ __forceinline__ u64 fmul2(u64 a, u64 b) {
    u64 d; asm("mul.rn.f32x2 %0, %1, %2;" : "=l"(d) : "l"(a), "l"(b)); return d;
}
__device__ __forceinline__ u64 dup2(float x) {
    u64 r; asm("mov.b64 %0, {%1, %1};" : "=l"(r) : "f"(x)); return r;
}
__device__ __forceinline__ float2 unpk2(u64 v) {
    float2 r; asm("mov.b64 {%0, %1}, %2;" : "=f"(r.x), "=f"(r.y) : "l"(v)); return r;
}
__device__ __forceinline__ float logdelta(float d) {
    float l = log2f(fabsf(d) + 1.0f) * (1.0f / 3.0f);
    return copysignf(l, d);
}

// ---------------------------------------------------------------------------
// C = alpha*(A[M,256] @ W[256,256] + bias).
// TMODE 0: row-major out. TMODE 1: per-head transposed out:
//   C[((m/plane)*8 + n/32)*32 + n%32][m%plane]   (plane = NQQ or HWK)
// ---------------------------------------------------------------------------
template<int TMODE>
__global__ void gemm_bias_kernel(const float* __restrict__ A,
                                 const float* __restrict__ Wm,
                                 const float* __restrict__ bias,
                                 float* __restrict__ C,
                                 int M, int plane, float alpha)
{
    __shared__ __align__(16) float As[16][64];
    __shared__ __align__(16) float Ws[16][64];

    int tid = threadIdx.x;
    int m0 = blockIdx.x * 64;
    int n0 = blockIdx.y * 64;
    int tm = tid >> 4, tn = tid & 15;
    int lrow = tid >> 2, lkq = tid & 3;
    int wkk = tid >> 4, wnq = tid & 15;

    u64 acc2[4][2] = {};

    for (int k0 = 0; k0 < 256; k0 += 16) {
        float4 av = make_float4(0.f, 0.f, 0.f, 0.f);
        int m = m0 + lrow;
        if (m < M) av = *(const float4*)&A[m * 256 + k0 + 4 * lkq];
        As[4 * lkq + 0][lrow] = av.x;
        As[4 * lkq + 1][lrow] = av.y;
        As[4 * lkq + 2][lrow] = av.z;
        As[4 * lkq + 3][lrow] = av.w;
        *(float4*)&Ws[wkk][4 * wnq] =
            *(const float4*)&Wm[(k0 + wkk) * 256 + n0 + 4 * wnq];
        __syncthreads();

        #pragma unroll
        for (int kk = 0; kk < 16; kk++) {
            float4 a = *(const float4*)&As[kk][4 * tm];
            ulonglong2 w = *(const ulonglong2*)&Ws[kk][4 * tn];
            float ar[4] = {a.x, a.y, a.z, a.w};
            #pragma unroll
            for (int i = 0; i < 4; i++) {
                u64 ad = dup2(ar[i]);
                acc2[i][0] = ffma2(ad, w.x, acc2[i][0]);
                acc2[i][1] = ffma2(ad, w.y, acc2[i][1]);
            }
        }
        __syncthreads();
    }

    float4 bv = *(const float4*)&bias[n0 + 4 * tn];
    float o[4][4];
    #pragma unroll
    for (int i = 0; i < 4; i++) {
        float2 lo = unpk2(acc2[i][0]);
        float2 hi = unpk2(acc2[i][1]);
        o[i][0] = alpha * (lo.x + bv.x);
        o[i][1] = alpha * (lo.y + bv.y);
        o[i][2] = alpha * (hi.x + bv.z);
        o[i][3] = alpha * (hi.y + bv.w);
    }

    if (TMODE == 0) {
        #pragma unroll
        for (int i = 0; i < 4; i++) {
            int m = m0 + 4 * tm + i;
            if (m < M)
                *(float4*)&C[m * 256 + n0 + 4 * tn] =
                    make_float4(o[i][0], o[i][1], o[i][2], o[i][3]);
        }
    } else {
        __shared__ float Ts[64][65];
        #pragma unroll
        for (int i = 0; i < 4; i++)
            #pragma unroll
            for (int j = 0; j < 4; j++)
                Ts[4 * tn + j][4 * tm + i] = o[i][j];
        __syncthreads();
        for (int idx = tid; idx < 4096; idx += 256) {
            int ml = idx & 63, nl = idx >> 6;
            int m = m0 + ml;
            if (m < M) {
                int bq = m / plane;
                int mm = m - bq * plane;
                int n = n0 + nl;
                int row = (bq * NH + (n >> 5)) * 32 + (n & 31);
                C[(long long)row * plane + mm] = Ts[nl][ml];
            }
        }
    }
}

// ---------------------------------------------------------------------------
// RPE MLP: 256 threads = 4 (b,q) x 2 axes x 32 lanes; 2 positions/thread.
// ---------------------------------------------------------------------------
__global__ void rpe_kernel(const float* __restrict__ refp,
                           const float* __restrict__ W1x, const float* __restrict__ b1x,
                           const float* __restrict__ W2x,
                           const float* __restrict__ W1y, const float* __restrict__ b1y,
                           const float* __restrict__ W2y)
{
    __shared__ __align__(16) float2 sW1[2][RPEH];
    __shared__ __align__(16) float sb1[2][RPEH];
    __shared__ __align__(16) float sW2[2][RPEH * 8];

    int tid = threadIdx.x;
    for (int i = tid; i < RPEH; i += 256) {
        sW1[0][i] = make_float2(W1x[i], W1x[RPEH + i]);  sb1[0][i] = b1x[i];
        sW1[1][i] = make_float2(W1y[i], W1y[RPEH + i]);  sb1[1][i] = b1y[i];
    }
    for (int i = tid; i < RPEH * 8; i += 256) {
        sW2[0][i] = W2x[i];
        sW2[1][i] = W2y[i];
    }
    __syncthreads();

    int bq = blockIdx.x * 4 + (tid >> 6);
    int b = bq / NQQ, q = bq - b * NQQ;
    float4 r = *(const float4*)&refp[bq * 4];
    int axis = (tid >> 5) & 1;
    int lane = tid & 31;

    float ctr = axis ? r.y : r.x;
    float sz  = axis ? r.w : r.z;
    float lo = (ctr - 0.5f * sz) * 1024.0f;
    float hi = (ctr + 0.5f * sz) * 1024.0f;
    float posA = (lane + 0.5f) * 16.0f;
    float posB = (lane + 32.5f) * 16.0f;
    float d1a = logdelta(lo - posA), d2a = logdelta(hi - posA);
    float d1b = logdelta(lo - posB), d2b = logdelta(hi - posB);

    const float2* w1 = sW1[axis];
    const float* bb = sb1[axis];
    const float* w2 = sW2[axis];

    u64 a0[4] = {}, a1[4] = {};
    #pragma unroll 4
    for (int hh = 0; hh < RPEH; hh++) {
        float2 w = w1[hh];
        float bvf = bb[hh];
        float v0 = fmaxf(fmaf(d1a, w.x, fmaf(d2a, w.y, bvf)), 0.0f);
        float v1 = fmaxf(fmaf(d1b, w.x, fmaf(d2b, w.y, bvf)), 0.0f);
        u64 v0d = dup2(v0), v1d = dup2(v1);
        ulonglong2 wlo = *(const ulonglong2*)&w2[hh * 8];
        ulonglong2 whi = *(const ulonglong2*)&w2[hh * 8 + 4];
        a0[0] = ffma2(v0d, wlo.x, a0[0]);  a0[1] = ffma2(v0d, wlo.y, a0[1]);
        a0[2] = ffma2(v0d, whi.x, a0[2]);  a0[3] = ffma2(v0d, whi.y, a0[3]);
        a1[0] = ffma2(v1d, wlo.x, a1[0]);  a1[1] = ffma2(v1d, wlo.y, a1[1]);
        a1[2] = ffma2(v1d, whi.x, a1[2]);  a1[3] = ffma2(v1d, whi.y, a1[3]);
    }

    float o0[8], o1[8];
    #pragma unroll
    for (int c = 0; c < 4; c++) {
        float2 x0 = unpk2(a0[c]); float2 x1 = unpk2(a1[c]);
        o0[2*c] = x0.x * LOG2E_F;  o0[2*c+1] = x0.y * LOG2E_F;
        o1[2*c] = x1.x * LOG2E_F;  o1[2*c+1] = x1.y * LOG2E_F;
    }
    long long bh = (long long)b * NH;
    #pragma unroll
    for (int hd = 0; hd < 8; hd++) {
        if (axis == 0) {
            g_rx[((bh + hd) * NQQ + q) * 64 + lane]      = o0[hd];
            g_rx[((bh + hd) * NQQ + q) * 64 + lane + 32] = o1[hd];
        } else {
            g_ryT[((bh + hd) * 64 + lane)      * NQQ + q] = o0[hd];
            g_ryT[((bh + hd) * 64 + lane + 32) * NQQ + q] = o1[hd];
        }
    }
}

// ---------------------------------------------------------------------------
// Fused attention: block=(qtile 64, head, batch), 128 threads.
// Double-buffered K/V/ry with register prefetch; FFMA2 GEMMs; base-2 softmax.
// ---------------------------------------------------------------------------
#define ATTN_SMEM_FLOATS 12992
__global__ void __launch_bounds__(128, 2) attn_kernel(float* __restrict__ outp)
{
    extern __shared__ __align__(16) float sm[];
    float* QsT  = sm;            // [32][64]
    float* KsT  = sm + 2048;     // 2 x [32 d][32 k]
    float* Vs   = sm + 4096;     // 2 x [32 k][32 d]
    float* ST   = sm + 6144;     // [32 k][68]
    float* rxsT = sm + 8320;     // [64 w][68]
    float* ryb  = sm + 12672;    // 2 x [64]
    float* mrow = sm + 12800;
    float* lrow = sm + 12864;
    float* srow = sm + 12928;

    int tid = threadIdx.x;
    int qt = blockIdx.x, h = blockIdx.y, b = blockIdx.z;
    int q0 = qt * 64;
    int tq = tid >> 3, tx = tid & 7;
    long long bh = (long long)b * NH + h;

    if (tid < 64) { mrow[tid] = -1e30f; lrow[tid] = 0.0f; }

    // Q tile: coalesced rows of g_qT, conflict-free stores. (900%4==0 => safe)
    {
        int q4 = (tid & 15) * 4;
        int dr = tid >> 4;
        const float* qb = g_qT + bh * 32 * NQQ;
        #pragma unroll
        for (int r2 = 0; r2 < 4; r2++) {
            int d = dr + 8 * r2;
            float4 val = make_float4(0.f, 0.f, 0.f, 0.f);
            if (q0 + q4 < NQQ) val = *(const float4*)&qb[d * NQQ + q0 + q4];
            *(float4*)&QsT[d * 64 + q4] = val;
        }
    }
    // rx tile, transposed into [w][q] (pad 68)
    {
        const float* rxb = g_rx + bh * NQQ * 64;
        for (int idx = tid; idx < 64 * 16; idx += 128) {
            int q = idx >> 4, w4 = (idx & 15) * 4;
            int qg = min(q0 + q, NQQ - 1);
            float4 v = *(const float4*)&rxb[qg * 64 + w4];
            rxsT[(w4 + 0) * 68 + q] = v.x;
            rxsT[(w4 + 1) * 68 + q] = v.y;
            rxsT[(w4 + 2) * 68 + q] = v.z;
            rxsT[(w4 + 3) * 68 + q] = v.w;
        }
    }

    int lk4 = (tid & 7) * 4;
    int lr16 = tid >> 3;         // 0..15
    const float* kb = g_kT + bh * 32 * HWK;
    const float* vb = g_v + (long long)b * HWK * EE + h * HDIM;
    int ryq = min(q0 + tid, NQQ - 1);

    // Prologue: chunk 0 -> buffer 0
    *(float4*)&KsT[lr16 * 32 + lk4]        = *(const float4*)&kb[lr16 * HWK + lk4];
    *(float4*)&KsT[(lr16 + 16) * 32 + lk4] = *(const float4*)&kb[(lr16 + 16) * HWK + lk4];
    *(float4*)&Vs[lr16 * 32 + lk4]         = *(const float4*)&vb[lr16 * EE + lk4];
    *(float4*)&Vs[(lr16 + 16) * 32 + lk4]  = *(const float4*)&vb[(lr16 + 16) * EE + lk4];
    if (tid < 64) ryb[tid] = g_ryT[bh * 64 * NQQ + ryq];
    __syncthreads();

    u64 o2[4][2] = {};

    for (int ch = 0; ch < 128; ch++) {
        int buf = ch & 1;
        int w0 = buf * 32;
        const float* Kc = KsT + buf * 1024;
        const float* Vc = Vs + buf * 1024;
        const float* ryc = ryb + buf * 64;

        // Prefetch chunk ch+1 into registers
        float4 kr0, kr1, vr0, vr1; float ryr = 0.0f;
        if (ch < 127) {
            int k0n = (ch + 1) * 32;
            kr0 = *(const float4*)&kb[lr16 * HWK + k0n + lk4];
            kr1 = *(const float4*)&kb[(lr16 + 16) * HWK + k0n + lk4];
            vr0 = *(const float4*)&vb[(k0n + lr16) * EE + lk4];
            vr1 = *(const float4*)&vb[(k0n + lr16 + 16) * EE + lk4];
            if (tid < 64)
                ryr = g_ryT[(bh * 64 + ((ch + 1) >> 1)) * NQQ + ryq];
        }

        // GEMM1: S[64q][32k] = Q @ K^T, FFMA2 pairs along k
        u64 s2[4][2] = {};
        #pragma unroll 8
        for (int kk = 0; kk < 32; kk++) {
            float4 qv = *(const float4*)&QsT[kk * 64 + 4 * tq];
            ulonglong2 kp = *(const ulonglong2*)&Kc[kk * 32 + 4 * tx];
            float qr[4] = {qv.x, qv.y, qv.z, qv.w};
            #pragma unroll
            for (int i = 0; i < 4; i++) {
                u64 qd = dup2(qr[i]);
                s2[i][0] = ffma2(qd, kp.x, s2[i][0]);
                s2[i][1] = ffma2(qd, kp.y, s2[i][1]);
            }
        }
        float s[4][4];
        #pragma unroll
        for (int i = 0; i < 4; i++) {
            float2 a = unpk2(s2[i][0]); float2 c = unpk2(s2[i][1]);
            s[i][0] = a.x; s[i][1] = a.y; s[i][2] = c.x; s[i][3] = c.y;
        }
        float ry4[4];
        #pragma unroll
        for (int i = 0; i < 4; i++) ry4[i] = ryc[4 * tq + i];
        #pragma unroll
        for (int j = 0; j < 4; j++) {
            float4 rv = *(const float4*)&rxsT[(w0 + 4 * tx + j) * 68 + 4 * tq];
            float4 sv;
            sv.x = s[0][j] + ry4[0] + rv.x;
            sv.y = s[1][j] + ry4[1] + rv.y;
            sv.z = s[2][j] + ry4[2] + rv.z;
            sv.w = s[3][j] + ry4[3] + rv.w;
            *(float4*)&ST[(4 * tx + j) * 68 + 4 * tq] = sv;
        }
        __syncthreads();

        // Softmax: 2 threads per query
        {
            int q = tid >> 1, hf = tid & 1;
            float mold = mrow[q];
            float mx = mold;
            #pragma unroll
            for (int s5 = 0; s5 < 16; s5++)
                mx = fmaxf(mx, ST[(2 * s5 + hf) * 68 + q]);
            mx = fmaxf(mx, __shfl_xor_sync(0xffffffffu, mx, 1));
            float sum = 0.0f;
            #pragma unroll
            for (int s5 = 0; s5 < 16; s5++) {
                int kk = 2 * s5 + hf;
                float p = fexp2(ST[kk * 68 + q] - mx);
                ST[kk * 68 + q] = p;
                sum += p;
            }
            sum += __shfl_xor_sync(0xffffffffu, sum, 1);
            if (hf == 0) {
                mrow[q] = mx;
                float scl = fexp2(mold - mx);
                lrow[q] = lrow[q] * scl + sum;
                srow[q] = scl;
            }
        }
        __syncthreads();

        // Store prefetched chunk into other buffer (no reader until next iter)
        if (ch < 127) {
            float* Kn = KsT + (buf ^ 1) * 1024;
            float* Vn = Vs + (buf ^ 1) * 1024;
            *(float4*)&Kn[lr16 * 32 + lk4]        = kr0;
            *(float4*)&Kn[(lr16 + 16) * 32 + lk4] = kr1;
            *(float4*)&Vn[lr16 * 32 + lk4]        = vr0;
            *(float4*)&Vn[(lr16 + 16) * 32 + lk4] = vr1;
            if (tid < 64) ryb[(buf ^ 1) * 64 + tid] = ryr;
        }

        // GEMM2: O = scl*O + P @ V, FFMA2 pairs along d
        {
            u64 sc[4];
            #pragma unroll
            for (int i = 0; i < 4; i++) sc[i] = dup2(srow[4 * tq + i]);
            #pragma unroll
            for (int i = 0; i < 4; i++) {
                o2[i][0] = fmul2(o2[i][0], sc[i]);
                o2[i][1] = fmul2(o2[i][1], sc[i]);
            }
            #pragma unroll 8
            for (int kk = 0; kk < 32; kk++) {
                float4 pv = *(const float4*)&ST[kk * 68 + 4 * tq];
                ulonglong2 vp = *(const ulonglong2*)&Vc[kk * 32 + 4 * tx];
                float pr[4] = {pv.x, pv.y, pv.z, pv.w};
                #pragma unroll
                for (int i = 0; i < 4; i++) {
                    u64 pd = dup2(pr[i]);
                    o2[i][0] = ffma2(pd, vp.x, o2[i][0]);
                    o2[i][1] = ffma2(pd, vp.y, o2[i][1]);
                }
            }
        }
        __syncthreads();
    }

    #pragma unroll
    for (int i = 0; i < 4; i++) {
        int q = q0 + 4 * tq + i;
        if (q < NQQ) {
            float inv = 1.0f / lrow[4 * tq + i];
            float2 lo = unpk2(o2[i][0]);
            float2 hi = unpk2(o2[i][1]);
            *(float4*)&outp[(b * NQQ + q) * EE + h * HDIM + 4 * tx] =
                make_float4(lo.x * inv, lo.y * inv, hi.x * inv, hi.y * inv);
        }
    }
}

// ---------------------------------------------------------------------------
extern "C" void kernel_launch(void* const* d_in, const int* in_sizes, int n_in,
                              void* d_out, int out_size)
{
    const float* query = (const float*)d_in[0];
    const float* key   = (const float*)d_in[1];
    const float* value = (const float*)d_in[2];
    const float* refp  = (const float*)d_in[3];
    const float* Wq = (const float*)d_in[4];  const float* bq = (const float*)d_in[5];
    const float* Wk = (const float*)d_in[6];  const float* bk = (const float*)d_in[7];
    const float* Wv = (const float*)d_in[8];  const float* bv = (const float*)d_in[9];
    const float* Wo = (const float*)d_in[10]; const float* bo = (const float*)d_in[11];
    const float* W1x = (const float*)d_in[12]; const float* b1x = (const float*)d_in[13];
    const float* W2x = (const float*)d_in[14];
    const float* W1y = (const float*)d_in[15]; const float* b1y = (const float*)d_in[16];
    const float* W2y = (const float*)d_in[17];
    float* out = (float*)d_out;

    float *pqT, *pkT, *pv, *patt;
    cudaGetSymbolAddress((void**)&pqT, g_qT);
    cudaGetSymbolAddress((void**)&pkT, g_kT);
    cudaGetSymbolAddress((void**)&pv, g_v);
    cudaGetSymbolAddress((void**)&patt, g_att);

    static int attr_done = 0;
    if (!attr_done) {
        cudaFuncSetAttribute(attn_kernel,
                             cudaFuncAttributeMaxDynamicSharedMemorySize,
                             ATTN_SMEM_FLOATS * 4);
        attr_done = 1;
    }

    gemm_bias_kernel<1><<<dim3(29, 4), 256>>>(query, Wq, bq, pqT, BB * NQQ,
                                              NQQ, QSCALE_F * LOG2E_F);
    gemm_bias_kernel<1><<<dim3(128, 4), 256>>>(key, Wk, bk, pkT, BB * HWK,
                                               HWK, 1.0f);
    gemm_bias_kernel<0><<<dim3(128, 4), 256>>>(value, Wv, bv, pv, BB * HWK,
                                               HWK, 1.0f);

    rpe_kernel<<<450, 256>>>(refp, W1x, b1x, W2x, W1y, b1y, W2y);

    attn_kernel<<<dim3(15, NH, BB), 128, ATTN_SMEM_FLOATS * 4>>>(patt);

    gemm_bias_kernel<0><<<dim3(29, 4), 256>>>(patt, Wo, bo, out, BB * NQQ,
                                              NQQ, 1.0f);
}